// round 8
// baseline (speedup 1.0000x reference)
#include <cuda_runtime.h>

// ---------------- problem constants ----------------
#define TBS   128          // T*B = 4*32
#define SEQ   81           // 9*9
#define CH    128          // width C
#define MROWS (TBS*SEQ)    // 10368 rows
#define NQKV  384          // 3*C
#define EPSLN 1e-5f

typedef unsigned long long ull;

// ---------------- scratch (static device globals; no allocation) ------------
__device__ float  g_h  [MROWS*CH];    // residual stream
__device__ float2 g_stats[MROWS];     // per-row (mu, rstd) of g_h
__device__ float  g_qkv[MROWS*NQKV];  // qkv projection
__device__ float  g_att[MROWS*CH];    // attention output

// ---------------- packed f32x2 helpers --------------------------------------
__device__ __forceinline__ ull pk2(float x, float y) {
    ull r;
    asm("mov.b64 %0, {%1, %2};"
        : "=l"(r) : "r"(__float_as_uint(x)), "r"(__float_as_uint(y)));
    return r;
}
__device__ __forceinline__ ull fma2(ull a, ull b, ull c) {
    ull d;
    asm("fma.rn.f32x2 %0, %1, %2, %3;" : "=l"(d) : "l"(a), "l"(b), "l"(c));
    return d;
}
__device__ __forceinline__ void upk2(ull v, float& x, float& y) {
    unsigned int lo, hi;
    asm("mov.b64 {%0, %1}, %2;" : "=r"(lo), "=r"(hi) : "l"(v));
    x = __uint_as_float(lo);
    y = __uint_as_float(hi);
}
__device__ __forceinline__ float ex2(float x) {
    float r;
    asm("ex2.approx.f32 %0, %1;" : "=f"(r) : "f"(x));
    return r;
}

// ---------------- input projection + LN stats --------------------------------
__global__ void __launch_bounds__(256) inproj_kernel(const float* __restrict__ x,
                                                     const float* __restrict__ in_w,
                                                     const float* __restrict__ in_b) {
    int row  = blockIdx.x * 8 + (threadIdx.x >> 5);
    int lane = threadIdx.x & 31;
    float x0 = __ldg(&x[row * 2]);
    float x1 = __ldg(&x[row * 2 + 1]);
    float s = 0.f, ss = 0.f;
    float* hr = g_h + (size_t)row * CH;
#pragma unroll
    for (int j = 0; j < 4; j++) {
        int c = lane + 32 * j;
        float h = fmaf(x0, in_w[c], fmaf(x1, in_w[CH + c], in_b[c]));
        hr[c] = h;
        s += h;
        ss = fmaf(h, h, ss);
    }
#pragma unroll
    for (int o = 16; o; o >>= 1) {
        s  += __shfl_xor_sync(0xffffffffu, s, o);
        ss += __shfl_xor_sync(0xffffffffu, ss, o);
    }
    if (lane == 0) {
        float mu  = s * (1.0f / CH);
        float var = fmaf(-mu, mu, ss * (1.0f / CH));
        g_stats[row] = make_float2(mu, rsqrtf(var + EPSLN));
    }
}

// ---------------- fused LN + QKV GEMM ----------------------------------------
// 64M x 128N tile, 256 threads, 4 rows x (4+4 split) cols per thread.
// Double-buffered smem + register prefetch.
__global__ void __launch_bounds__(256) qkv_gemm(const float* __restrict__ W,
                                                const float* __restrict__ bias,
                                                const float* __restrict__ gam,
                                                const float* __restrict__ bet) {
    __shared__ float gsh[CH], bsh[CH];
    __shared__ __align__(16) float As[2][16][64];
    __shared__ __align__(16) float Bs[2][16][128];

    int tid = threadIdx.x;
    if (tid < 128) { gsh[tid] = gam[tid]; bsh[tid] = bet[tid]; }

    int tx = tid & 15;              // cols 4*tx..+3 and 64+4*tx..+3
    int ty = tid >> 4;              // rows 4*ty..+3 (0..15)

    int arow = tid & 63;            // A staging: row
    int akh  = (tid >> 6) << 2;     // A staging: k offset 0,4,8,12
    int brow = tid >> 4;            // B staging: k row 0..15
    int bcol = (tid & 15) << 3;     // B staging: col

    size_t mBase = (size_t)blockIdx.y * 64;
    int    nBase = blockIdx.x * 128;
    const float* hp = g_h + (mBase + arow) * CH + akh;
    float2 st = g_stats[mBase + arow];
    float c1 = st.y;                // rstd
    float c0 = -st.x * st.y;        // -mu*rstd
    const float* Bp = W + (size_t)brow * NQKV + nBase + bcol;

    ull acc[4][4];
#pragma unroll
    for (int m = 0; m < 4; m++)
#pragma unroll
        for (int j = 0; j < 4; j++) acc[m][j] = 0ull;

    // prologue: fetch + stage chunk 0
    float4 pa  = *(const float4*)(hp);
    float4 pb0 = *(const float4*)(Bp);
    float4 pb1 = *(const float4*)(Bp + 4);
    __syncthreads();                // gsh/bsh visible
    {
        float av[4] = {pa.x, pa.y, pa.z, pa.w};
#pragma unroll
        for (int j = 0; j < 4; j++) {
            int kk = akh + j;
            As[0][kk][arow] = fmaf(fmaf(av[j], c1, c0), gsh[kk], bsh[kk]);
        }
        *(float4*)&Bs[0][brow][bcol]     = pb0;
        *(float4*)&Bs[0][brow][bcol + 4] = pb1;
    }
    __syncthreads();

#pragma unroll
    for (int i = 0; i < 8; i++) {
        int buf = i & 1;
        if (i < 7) {                // prefetch next chunk into regs
            pa  = *(const float4*)(hp + (i + 1) * 16);
            const float* bq = Bp + (size_t)(i + 1) * 16 * NQKV;
            pb0 = *(const float4*)(bq);
            pb1 = *(const float4*)(bq + 4);
        }
#pragma unroll
        for (int k = 0; k < 16; k++) {
            float4 af = *(const float4*)&As[buf][k][4 * ty];
            ulonglong2 q0 = *(const ulonglong2*)&Bs[buf][k][4 * tx];       // contiguous
            ulonglong2 q1 = *(const ulonglong2*)&Bs[buf][k][64 + 4 * tx];  // contiguous
            ull bp2[4] = {q0.x, q0.y, q1.x, q1.y};
            float am[4] = {af.x, af.y, af.z, af.w};
#pragma unroll
            for (int m = 0; m < 4; m++) {
                ull aa = pk2(am[m], am[m]);
#pragma unroll
                for (int j = 0; j < 4; j++)
                    acc[m][j] = fma2(aa, bp2[j], acc[m][j]);
            }
        }
        if (i < 7) {                // stage next chunk into other buffer
            int nb = buf ^ 1;
            int k0 = (i + 1) * 16;
            float av[4] = {pa.x, pa.y, pa.z, pa.w};
#pragma unroll
            for (int j = 0; j < 4; j++) {
                int kk = akh + j;
                As[nb][kk][arow] = fmaf(fmaf(av[j], c1, c0), gsh[k0 + kk], bsh[k0 + kk]);
            }
            *(float4*)&Bs[nb][brow][bcol]     = pb0;
            *(float4*)&Bs[nb][brow][bcol + 4] = pb1;
            __syncthreads();
        }
    }

    int colA = nBase + 4 * tx;
    int colB = colA + 64;
    float4 biA = *(const float4*)(bias + colA);
    float4 biB = *(const float4*)(bias + colB);
#pragma unroll
    for (int m = 0; m < 4; m++) {
        size_t row = mBase + 4 * ty + m;
        float v[8];
        upk2(acc[m][0], v[0], v[1]);
        upk2(acc[m][1], v[2], v[3]);
        upk2(acc[m][2], v[4], v[5]);
        upk2(acc[m][3], v[6], v[7]);
        float* o = g_qkv + row * NQKV;
        *(float4*)(o + colA) = make_float4(v[0] + biA.x, v[1] + biA.y,
                                           v[2] + biA.z, v[3] + biA.w);
        *(float4*)(o + colB) = make_float4(v[4] + biB.x, v[5] + biB.y,
                                           v[6] + biB.z, v[7] + biB.w);
    }
}

// ---------------- fused per-channel attention (unchanged, proven) ------------
#define QT 9
#define KT 27
__global__ void __launch_bounds__(128, 8) attn_kernel() {
    int b  = blockIdx.y;
    int q0 = blockIdx.x * QT;
    int c  = threadIdx.x;

    __shared__ float ks[KT][CH];
    __shared__ float vs[KT][CH];

    const float* base = g_qkv + (size_t)b * SEQ * NQKV;
    const float LOG2E = 1.4426950408889634f;

    float qv[QT], num[QT], den[QT];
#pragma unroll
    for (int i = 0; i < QT; i++) {
        qv[i]  = base[(size_t)(q0 + i) * NQKV + c] * LOG2E;
        num[i] = 0.f;
        den[i] = 0.f;
    }

#pragma unroll 1
    for (int kc = 0; kc < SEQ; kc += KT) {
        __syncthreads();
#pragma unroll
        for (int r = 0; r < KT; r++) {
            ks[r][c] = base[(size_t)(kc + r) * NQKV + CH     + c];
            vs[r][c] = base[(size_t)(kc + r) * NQKV + 2 * CH + c];
        }
        __syncthreads();
#pragma unroll 3
        for (int r = 0; r < KT; r++) {
            float kk = ks[r][c];
            float vv = vs[r][c];
#pragma unroll
            for (int i = 0; i < QT; i++) {
                float e = ex2(qv[i] * kk);
                num[i] = fmaf(e, vv, num[i]);
                den[i] += e;
            }
        }
    }

    float* op = g_att + ((size_t)b * SEQ + q0) * CH + c;
#pragma unroll
    for (int i = 0; i < QT; i++) op[(size_t)i * CH] = __fdividef(num[i], den[i]);
}

// ---------------- full GEMM + relu + residual + LN stats ---------------------
// 32M x 128N tile, 128 threads, 4 rows x (4+4 split) cols per thread.
// g_h += relu(g_att @ W + bias); emits (mu, rstd) per updated row.
__global__ void __launch_bounds__(128) full_gemm(const float* __restrict__ W,
                                                 const float* __restrict__ bias) {
    __shared__ __align__(16) float As[2][16][32];
    __shared__ __align__(16) float Bs[2][16][128];

    int tid = threadIdx.x;
    int tx = tid & 15;              // cols 4*tx..+3 and 64+4*tx..+3
    int ty = tid >> 4;              // rows 4*ty..+3 (0..7)

    int arow = tid & 31;            // A staging: row
    int akh  = (tid >> 5) << 2;     // A staging: k offset 0,4,8,12
    int brow = tid >> 3;            // B staging: k row 0..15
    int bcol = (tid & 7) << 4;      // B staging: col (16 wide)

    size_t mBase = (size_t)blockIdx.x * 32;
    const float* ap = g_att + (mBase + arow) * CH + akh;
    const float* Bp = W + (size_t)brow * CH + bcol;

    ull acc[4][4];
#pragma unroll
    for (int m = 0; m < 4; m++)
#pragma unroll
        for (int j = 0; j < 4; j++) acc[m][j] = 0ull;

    // prologue: fetch + stage chunk 0
    float4 pa  = *(const float4*)(ap);
    float4 pb0 = *(const float4*)(Bp);
    float4 pb1 = *(const float4*)(Bp + 4);
    float4 pb2 = *(const float4*)(Bp + 8);
    float4 pb3 = *(const float4*)(Bp + 12);
    {
        float av[4] = {pa.x, pa.y, pa.z, pa.w};
#pragma unroll
        for (int j = 0; j < 4; j++) As[0][akh + j][arow] = av[j];
        *(float4*)&Bs[0][brow][bcol]      = pb0;
        *(float4*)&Bs[0][brow][bcol + 4]  = pb1;
        *(float4*)&Bs[0][brow][bcol + 8]  = pb2;
        *(float4*)&Bs[0][brow][bcol + 12] = pb3;
    }
    __syncthreads();

#pragma unroll
    for (int i = 0; i < 8; i++) {
        int buf = i & 1;
        if (i < 7) {
            pa = *(const float4*)(ap + (i + 1) * 16);
            const float* bq = Bp + (size_t)(i + 1) * 16 * CH;
            pb0 = *(const float4*)(bq);
            pb1 = *(const float4*)(bq + 4);
            pb2 = *(const float4*)(bq + 8);
            pb3 = *(const float4*)(bq + 12);
        }
#pragma unroll
        for (int k = 0; k < 16; k++) {
            float4 af = *(const float4*)&As[buf][k][4 * ty];
            ulonglong2 q0 = *(const ulonglong2*)&Bs[buf][k][4 * tx];
            ulonglong2 q1 = *(const ulonglong2*)&Bs[buf][k][64 + 4 * tx];
            ull bp2[4] = {q0.x, q0.y, q1.x, q1.y};
            float am[4] = {af.x, af.y, af.z, af.w};
#pragma unroll
            for (int m = 0; m < 4; m++) {
                ull aa = pk2(am[m], am[m]);
#pragma unroll
                for (int j = 0; j < 4; j++)
                    acc[m][j] = fma2(aa, bp2[j], acc[m][j]);
            }
        }
        if (i < 7) {
            int nb = buf ^ 1;
            float av[4] = {pa.x, pa.y, pa.z, pa.w};
#pragma unroll
            for (int j = 0; j < 4; j++) As[nb][akh + j][arow] = av[j];
            *(float4*)&Bs[nb][brow][bcol]      = pb0;
            *(float4*)&Bs[nb][brow][bcol + 4]  = pb1;
            *(float4*)&Bs[nb][brow][bcol + 8]  = pb2;
            *(float4*)&Bs[nb][brow][bcol + 12] = pb3;
            __syncthreads();
        }
    }

    int colA = 4 * tx;
    int colB = colA + 64;
    float4 biA = *(const float4*)(bias + colA);
    float4 biB = *(const float4*)(bias + colB);
    float s[4], ss[4];
#pragma unroll
    for (int m = 0; m < 4; m++) {
        size_t row = mBase + 4 * ty + m;
        float v[8];
        upk2(acc[m][0], v[0], v[1]);
        upk2(acc[m][1], v[2], v[3]);
        upk2(acc[m][2], v[4], v[5]);
        upk2(acc[m][3], v[6], v[7]);
        float* hrow = g_h + row * CH;
        float4 oA = *(const float4*)(hrow + colA);
        float4 oB = *(const float4*)(hrow + colB);
        float hn[8];
        hn[0] = oA.x + fmaxf(v[0] + biA.x, 0.f);
        hn[1] = oA.y + fmaxf(v[1] + biA.y, 0.f);
        hn[2] = oA.z + fmaxf(v[2] + biA.z, 0.f);
        hn[3] = oA.w + fmaxf(v[3] + biA.w, 0.f);
        hn[4] = oB.x + fmaxf(v[4] + biB.x, 0.f);
        hn[5] = oB.y + fmaxf(v[5] + biB.y, 0.f);
        hn[6] = oB.z + fmaxf(v[6] + biB.z, 0.f);
        hn[7] = oB.w + fmaxf(v[7] + biB.w, 0.f);
        *(float4*)(hrow + colA) = make_float4(hn[0], hn[1], hn[2], hn[3]);
        *(float4*)(hrow + colB) = make_float4(hn[4], hn[5], hn[6], hn[7]);
        float t = 0.f, tt = 0.f;
#pragma unroll
        for (int j = 0; j < 8; j++) {
            t += hn[j];
            tt = fmaf(hn[j], hn[j], tt);
        }
        s[m] = t;
        ss[m] = tt;
    }
    // reduce over the 16 tx lanes sharing each row (xor masks stay in-half)
#pragma unroll
    for (int m = 0; m < 4; m++) {
#pragma unroll
        for (int o = 8; o; o >>= 1) {
            s[m]  += __shfl_xor_sync(0xffffffffu, s[m], o);
            ss[m] += __shfl_xor_sync(0xffffffffu, ss[m], o);
        }
    }
    if (tx == 0) {
#pragma unroll
        for (int m = 0; m < 4; m++) {
            size_t row = mBase + 4 * ty + m;
            float mu  = s[m] * (1.0f / CH);
            float var = fmaf(-mu, mu, ss[m] * (1.0f / CH));
            g_stats[row] = make_float2(mu, rsqrtf(var + EPSLN));
        }
    }
}

// ---------------- final projection: out = h @ out_w + out_b ------------------
__global__ void __launch_bounds__(256) outproj_kernel(const float* __restrict__ ow,
                                                      const float* __restrict__ ob,
                                                      float* __restrict__ out) {
    int row  = blockIdx.x * 8 + (threadIdx.x >> 5);
    int lane = threadIdx.x & 31;
    const float* hr = g_h + (size_t)row * CH;
    float a0 = 0.f, a1 = 0.f, a2 = 0.f, a3 = 0.f;
#pragma unroll
    for (int j = 0; j < 4; j++) {
        int cidx = lane + 32 * j;
        float hv = hr[cidx];
        const float* w = ow + cidx * 4;
        a0 = fmaf(hv, w[0], a0);
        a1 = fmaf(hv, w[1], a1);
        a2 = fmaf(hv, w[2], a2);
        a3 = fmaf(hv, w[3], a3);
    }
#pragma unroll
    for (int o = 16; o; o >>= 1) {
        a0 += __shfl_xor_sync(0xffffffffu, a0, o);
        a1 += __shfl_xor_sync(0xffffffffu, a1, o);
        a2 += __shfl_xor_sync(0xffffffffu, a2, o);
        a3 += __shfl_xor_sync(0xffffffffu, a3, o);
    }
    if (lane == 0) {
        *(float4*)(out + (size_t)row * 4) =
            make_float4(a0 + ob[0], a1 + ob[1], a2 + ob[2], a3 + ob[3]);
    }
}

// ---------------- launch -----------------------------------------------------
extern "C" void kernel_launch(void* const* d_in, const int* in_sizes, int n_in,
                              void* d_out, int out_size) {
    const float* x      = (const float*)d_in[0];
    const float* in_w   = (const float*)d_in[1];
    const float* in_b   = (const float*)d_in[2];
    const float* ln_g   = (const float*)d_in[3];
    const float* ln_b   = (const float*)d_in[4];
    const float* qkv_w  = (const float*)d_in[5];
    const float* qkv_b  = (const float*)d_in[6];
    const float* full_w = (const float*)d_in[7];
    const float* full_b = (const float*)d_in[8];
    const float* out_w  = (const float*)d_in[9];
    const float* out_b  = (const float*)d_in[10];
    float* out = (float*)d_out;

    inproj_kernel<<<MROWS / 8, 256>>>(x, in_w, in_b);

    for (int l = 0; l < 4; l++) {
        qkv_gemm<<<dim3(NQKV / 128, MROWS / 64), 256>>>(
            qkv_w + (size_t)l * CH * NQKV, qkv_b + l * NQKV,
            ln_g + l * CH, ln_b + l * CH);
        attn_kernel<<<dim3(SEQ / QT, TBS), 128>>>();
        full_gemm<<<MROWS / 32, 128>>>(
            full_w + (size_t)l * CH * CH, full_b + l * CH);
    }

    outproj_kernel<<<MROWS / 8, 256>>>(out_w, out_b, out);
}

// round 9
// speedup vs baseline: 1.5708x; 1.5708x over previous
#include <cuda_runtime.h>

// ---------------- problem constants ----------------
#define TBS   128          // T*B = 4*32
#define SEQ   81           // 9*9
#define CH    128          // width C
#define MROWS (TBS*SEQ)    // 10368 rows
#define NQKV  384          // 3*C
#define EPSLN 1e-5f

typedef unsigned long long ull;

// ---------------- scratch (static device globals; no allocation) ------------
__device__ float  g_h  [MROWS*CH];    // residual stream
__device__ float2 g_stats[MROWS];     // per-row (mu, rstd) of g_h
__device__ float  g_qkv[MROWS*NQKV];  // qkv projection
__device__ float  g_att[MROWS*CH];    // attention output

// ---------------- packed f32x2 helpers --------------------------------------
__device__ __forceinline__ ull pk2(float x, float y) {
    ull r;
    asm("mov.b64 %0, {%1, %2};"
        : "=l"(r) : "r"(__float_as_uint(x)), "r"(__float_as_uint(y)));
    return r;
}
__device__ __forceinline__ ull fma2(ull a, ull b, ull c) {
    ull d;
    asm("fma.rn.f32x2 %0, %1, %2, %3;" : "=l"(d) : "l"(a), "l"(b), "l"(c));
    return d;
}
__device__ __forceinline__ void upk2(ull v, float& x, float& y) {
    unsigned int lo, hi;
    asm("mov.b64 {%0, %1}, %2;" : "=r"(lo), "=r"(hi) : "l"(v));
    x = __uint_as_float(lo);
    y = __uint_as_float(hi);
}
__device__ __forceinline__ float ex2(float x) {
    float r;
    asm("ex2.approx.f32 %0, %1;" : "=f"(r) : "f"(x));
    return r;
}

// ---------------- input projection + LN stats --------------------------------
__global__ void __launch_bounds__(256) inproj_kernel(const float* __restrict__ x,
                                                     const float* __restrict__ in_w,
                                                     const float* __restrict__ in_b) {
    int row  = blockIdx.x * 8 + (threadIdx.x >> 5);
    int lane = threadIdx.x & 31;
    float x0 = __ldg(&x[row * 2]);
    float x1 = __ldg(&x[row * 2 + 1]);
    float s = 0.f, ss = 0.f;
    float* hr = g_h + (size_t)row * CH;
#pragma unroll
    for (int j = 0; j < 4; j++) {
        int c = lane + 32 * j;
        float h = fmaf(x0, in_w[c], fmaf(x1, in_w[CH + c], in_b[c]));
        hr[c] = h;
        s += h;
        ss = fmaf(h, h, ss);
    }
#pragma unroll
    for (int o = 16; o; o >>= 1) {
        s  += __shfl_xor_sync(0xffffffffu, s, o);
        ss += __shfl_xor_sync(0xffffffffu, ss, o);
    }
    if (lane == 0) {
        float mu  = s * (1.0f / CH);
        float var = fmaf(-mu, mu, ss * (1.0f / CH));
        g_stats[row] = make_float2(mu, rsqrtf(var + EPSLN));
    }
}

// ---------------- row stats (mu, rstd) of g_h -------------------------------
__global__ void __launch_bounds__(256) stats_kernel() {
    int row  = blockIdx.x * 8 + (threadIdx.x >> 5);
    int lane = threadIdx.x & 31;
    const float* hr = g_h + (size_t)row * CH;
    float v0 = hr[lane], v1 = hr[lane + 32], v2 = hr[lane + 64], v3 = hr[lane + 96];
    float s  = v0 + v1 + v2 + v3;
    float ss = fmaf(v0, v0, fmaf(v1, v1, fmaf(v2, v2, v3 * v3)));
#pragma unroll
    for (int o = 16; o; o >>= 1) {
        s  += __shfl_xor_sync(0xffffffffu, s, o);
        ss += __shfl_xor_sync(0xffffffffu, ss, o);
    }
    if (lane == 0) {
        float mu  = s * (1.0f / CH);
        float var = fmaf(-mu, mu, ss * (1.0f / CH));
        g_stats[row] = make_float2(mu, rsqrtf(var + EPSLN));
    }
}

// ---------------- fused LN + QKV GEMM ----------------------------------------
// 64M x 64N tile, 256 threads, 4x4 per thread, M-packed f32x2 accumulators.
// A[m][k] = (g_h[m][k]-mu)*rstd*gam[k]+bet[k]; g_qkv = A@W + bias.
__global__ void __launch_bounds__(256) qkv_gemm(const float* __restrict__ W,
                                                const float* __restrict__ bias,
                                                const float* __restrict__ gam,
                                                const float* __restrict__ bet) {
    __shared__ float gsh[CH], bsh[CH];
    __shared__ __align__(16) float As[16][64];   // [k][m]
    __shared__ __align__(16) float Bs[16][64];   // [k][n]

    int tid = threadIdx.x;
    if (tid < 128) { gsh[tid] = gam[tid]; bsh[tid] = bet[tid]; }

    int tx = tid & 15;             // cols 4*tx..+3
    int ty = tid >> 4;             // rows 4*ty..+3

    int arow = tid & 63;           // A staging: row
    int akh  = (tid >> 6) << 2;    // A staging: k offset 0,4,8,12
    int brow = tid >> 4;           // B staging: k row 0..15
    int bcol = (tid & 15) << 2;    // B staging: col

    size_t mBase = (size_t)blockIdx.y * 64;
    int    nBase = blockIdx.x * 64;
    const float* hp = g_h + (mBase + arow) * CH + akh;
    float2 st = g_stats[mBase + arow];
    float c1 = st.y;               // rstd
    float c0 = -st.x * st.y;       // -mu*rstd
    const float* Bp = W + (size_t)brow * NQKV + nBase + bcol;

    ull acc[2][4];                 // [row-pair p][col j]: rows (4ty+2p, +1)
#pragma unroll
    for (int p = 0; p < 2; p++)
#pragma unroll
        for (int j = 0; j < 4; j++) acc[p][j] = 0ull;

    __syncthreads();               // gsh/bsh ready

    for (int k0 = 0; k0 < CH; k0 += 16) {
        float4 hv = *(const float4*)(hp + k0);
        float4 bv = *(const float4*)(Bp + (size_t)k0 * NQKV);
        float av[4] = {hv.x, hv.y, hv.z, hv.w};
#pragma unroll
        for (int j = 0; j < 4; j++) {
            int kk = akh + j;
            As[kk][arow] = fmaf(fmaf(av[j], c1, c0), gsh[k0 + kk], bsh[k0 + kk]);
        }
        *(float4*)&Bs[brow][bcol] = bv;
        __syncthreads();
#pragma unroll
        for (int k = 0; k < 16; k++) {
            ulonglong2 aa = *(const ulonglong2*)&As[k][4 * ty];  // rows pairs
            float4 b4 = *(const float4*)&Bs[k][4 * tx];
            ull bb[4] = {pk2(b4.x, b4.x), pk2(b4.y, b4.y),
                         pk2(b4.z, b4.z), pk2(b4.w, b4.w)};
#pragma unroll
            for (int j = 0; j < 4; j++) {
                acc[0][j] = fma2(aa.x, bb[j], acc[0][j]);
                acc[1][j] = fma2(aa.y, bb[j], acc[1][j]);
            }
        }
        __syncthreads();
    }

    int colBase = nBase + 4 * tx;
    float4 bi = *(const float4*)(bias + colBase);
#pragma unroll
    for (int p = 0; p < 2; p++) {
        float r0[4], r1[4];        // rows 4ty+2p, 4ty+2p+1
#pragma unroll
        for (int j = 0; j < 4; j++) upk2(acc[p][j], r0[j], r1[j]);
        size_t row = mBase + 4 * ty + 2 * p;
        float* o0 = g_qkv + row * NQKV + colBase;
        float* o1 = o0 + NQKV;
        *(float4*)o0 = make_float4(r0[0] + bi.x, r0[1] + bi.y,
                                   r0[2] + bi.z, r0[3] + bi.w);
        *(float4*)o1 = make_float4(r1[0] + bi.x, r1[1] + bi.y,
                                   r1[2] + bi.z, r1[3] + bi.w);
    }
}

// ---------------- fused per-channel attention, channel-split ------------------
// Block = 64 threads = 64 channels; grid (9, TBS, 2). smem 13.8KB -> ~32 warps/SM.
#define QT 9
#define KT 27
__global__ void __launch_bounds__(64) attn_kernel() {
    int b  = blockIdx.y;
    int q0 = blockIdx.x * QT;
    int c  = threadIdx.x + (blockIdx.z << 6);
    int t  = threadIdx.x;

    __shared__ float ks[KT][64];
    __shared__ float vs[KT][64];

    const float* base = g_qkv + (size_t)b * SEQ * NQKV;
    const float LOG2E = 1.4426950408889634f;

    float qv[QT], num[QT], den[QT];
#pragma unroll
    for (int i = 0; i < QT; i++) {
        qv[i]  = base[(size_t)(q0 + i) * NQKV + c] * LOG2E;
        num[i] = 0.f;
        den[i] = 0.f;
    }

#pragma unroll 1
    for (int kc = 0; kc < SEQ; kc += KT) {
        __syncthreads();
#pragma unroll
        for (int r = 0; r < KT; r++) {
            ks[r][t] = base[(size_t)(kc + r) * NQKV + CH     + c];
            vs[r][t] = base[(size_t)(kc + r) * NQKV + 2 * CH + c];
        }
        __syncthreads();
#pragma unroll 3
        for (int r = 0; r < KT; r++) {
            float kk = ks[r][t];
            float vv = vs[r][t];
#pragma unroll
            for (int i = 0; i < QT; i++) {
                float e = ex2(qv[i] * kk);
                num[i] = fmaf(e, vv, num[i]);
                den[i] += e;
            }
        }
    }

    float* op = g_att + ((size_t)b * SEQ + q0) * CH + c;
#pragma unroll
    for (int i = 0; i < QT; i++) op[(size_t)i * CH] = __fdividef(num[i], den[i]);
}

// ---------------- full GEMM + relu + residual (R3-proven shape) ---------------
// 64M x 64N tile, 256 threads, 4x4 per thread, N-packed f32x2.
__global__ void __launch_bounds__(256) full_gemm(const float* __restrict__ B,
                                                 const float* __restrict__ bias) {
    __shared__ __align__(16) float As[16][64];   // [k][m]
    __shared__ __align__(16) float Bs[16][64];

    int tid = threadIdx.x;
    int tx  = tid & 15;
    int ty  = tid >> 4;

    ull acc[4][2];
#pragma unroll
    for (int m = 0; m < 4; m++) { acc[m][0] = 0ull; acc[m][1] = 0ull; }

    int ar = tid >> 2;             // 0..63 : A tile row
    int ac = (tid & 3) << 2;       // 0,4,8,12 : A tile k-offset
    int br = tid >> 4;             // 0..15 : B tile k-row
    int bc = (tid & 15) << 2;      // B tile col

    const float* Aload = g_att + ((size_t)blockIdx.y * 64 + ar) * CH + ac;
    const float* Bload = B + (size_t)br * CH + blockIdx.x * 64 + bc;

    for (int k0 = 0; k0 < CH; k0 += 16) {
        float4 av = *(const float4*)(Aload + k0);
        float4 bv = *(const float4*)(Bload + (size_t)k0 * CH);
        As[ac + 0][ar] = av.x;
        As[ac + 1][ar] = av.y;
        As[ac + 2][ar] = av.z;
        As[ac + 3][ar] = av.w;
        *(float4*)&Bs[br][bc] = bv;
        __syncthreads();
#pragma unroll
        for (int k = 0; k < 16; k++) {
            float4 b4 = *(const float4*)&Bs[k][tx << 2];
            ull b01 = pk2(b4.x, b4.y);
            ull b23 = pk2(b4.z, b4.w);
#pragma unroll
            for (int m = 0; m < 4; m++) {
                float a = As[k][(ty << 2) + m];
                ull aa = pk2(a, a);
                acc[m][0] = fma2(aa, b01, acc[m][0]);
                acc[m][1] = fma2(aa, b23, acc[m][1]);
            }
        }
        __syncthreads();
    }

    int col = blockIdx.x * 64 + (tx << 2);
    float4 bi = *(const float4*)(bias + col);
#pragma unroll
    for (int m = 0; m < 4; m++) {
        size_t row = (size_t)blockIdx.y * 64 + (ty << 2) + m;
        float r0, r1, r2, r3;
        upk2(acc[m][0], r0, r1);
        upk2(acc[m][1], r2, r3);
        r0 = fmaxf(r0 + bi.x, 0.f);
        r1 = fmaxf(r1 + bi.y, 0.f);
        r2 = fmaxf(r2 + bi.z, 0.f);
        r3 = fmaxf(r3 + bi.w, 0.f);
        float* hrow = g_h + row * CH + col;
        float4 old = *(const float4*)hrow;
        *(float4*)hrow = make_float4(old.x + r0, old.y + r1,
                                     old.z + r2, old.w + r3);
    }
}

// ---------------- final projection: out = h @ out_w + out_b ------------------
__global__ void __launch_bounds__(256) outproj_kernel(const float* __restrict__ ow,
                                                      const float* __restrict__ ob,
                                                      float* __restrict__ out) {
    int row  = blockIdx.x * 8 + (threadIdx.x >> 5);
    int lane = threadIdx.x & 31;
    const float* hr = g_h + (size_t)row * CH;
    float a0 = 0.f, a1 = 0.f, a2 = 0.f, a3 = 0.f;
#pragma unroll
    for (int j = 0; j < 4; j++) {
        int cidx = lane + 32 * j;
        float hv = hr[cidx];
        const float* w = ow + cidx * 4;
        a0 = fmaf(hv, w[0], a0);
        a1 = fmaf(hv, w[1], a1);
        a2 = fmaf(hv, w[2], a2);
        a3 = fmaf(hv, w[3], a3);
    }
#pragma unroll
    for (int o = 16; o; o >>= 1) {
        a0 += __shfl_xor_sync(0xffffffffu, a0, o);
        a1 += __shfl_xor_sync(0xffffffffu, a1, o);
        a2 += __shfl_xor_sync(0xffffffffu, a2, o);
        a3 += __shfl_xor_sync(0xffffffffu, a3, o);
    }
    if (lane == 0) {
        *(float4*)(out + (size_t)row * 4) =
            make_float4(a0 + ob[0], a1 + ob[1], a2 + ob[2], a3 + ob[3]);
    }
}

// ---------------- launch -----------------------------------------------------
extern "C" void kernel_launch(void* const* d_in, const int* in_sizes, int n_in,
                              void* d_out, int out_size) {
    const float* x      = (const float*)d_in[0];
    const float* in_w   = (const float*)d_in[1];
    const float* in_b   = (const float*)d_in[2];
    const float* ln_g   = (const float*)d_in[3];
    const float* ln_b   = (const float*)d_in[4];
    const float* qkv_w  = (const float*)d_in[5];
    const float* qkv_b  = (const float*)d_in[6];
    const float* full_w = (const float*)d_in[7];
    const float* full_b = (const float*)d_in[8];
    const float* out_w  = (const float*)d_in[9];
    const float* out_b  = (const float*)d_in[10];
    float* out = (float*)d_out;

    inproj_kernel<<<MROWS / 8, 256>>>(x, in_w, in_b);

    for (int l = 0; l < 4; l++) {
        qkv_gemm<<<dim3(NQKV / 64, MROWS / 64), 256>>>(
            qkv_w + (size_t)l * CH * NQKV, qkv_b + l * NQKV,
            ln_g + l * CH, ln_b + l * CH);
        attn_kernel<<<dim3(SEQ / QT, TBS, 2), 64>>>();
        full_gemm<<<dim3(CH / 64, MROWS / 64), 256>>>(
            full_w + (size_t)l * CH * CH, full_b + l * CH);
        if (l < 3) stats_kernel<<<MROWS / 8, 256>>>();
    }

    outproj_kernel<<<MROWS / 8, 256>>>(out_w, out_b, out);
}

// round 11
// speedup vs baseline: 1.6508x; 1.0509x over previous
#include <cuda_runtime.h>

// ---------------- problem constants ----------------
#define TBS   128          // T*B = 4*32
#define SEQ   81           // 9*9
#define CH    128          // width C
#define MROWS (TBS*SEQ)    // 10368 rows
#define NQKV  384          // 3*C
#define EPSLN 1e-5f

typedef unsigned long long ull;

// ---------------- scratch (static device globals; no allocation) ------------
__device__ float  g_h  [MROWS*CH];    // residual stream
__device__ float2 g_stats[MROWS];     // per-row (mu, rstd) of g_h
__device__ float4 g_part[MROWS];      // per-row (s0, ss0, s1, ss1) partials
__device__ float  g_qkv[MROWS*NQKV];  // qkv projection
__device__ float  g_att[MROWS*CH];    // attention output

// ---------------- packed f32x2 helpers --------------------------------------
__device__ __forceinline__ ull pk2(float x, float y) {
    ull r;
    asm("mov.b64 %0, {%1, %2};"
        : "=l"(r) : "r"(__float_as_uint(x)), "r"(__float_as_uint(y)));
    return r;
}
__device__ __forceinline__ ull fma2(ull a, ull b, ull c) {
    ull d;
    asm("fma.rn.f32x2 %0, %1, %2, %3;" : "=l"(d) : "l"(a), "l"(b), "l"(c));
    return d;
}
__device__ __forceinline__ void upk2(ull v, float& x, float& y) {
    unsigned int lo, hi;
    asm("mov.b64 {%0, %1}, %2;" : "=r"(lo), "=r"(hi) : "l"(v));
    x = __uint_as_float(lo);
    y = __uint_as_float(hi);
}
__device__ __forceinline__ float ex2(float x) {
    float r;
    asm("ex2.approx.f32 %0, %1;" : "=f"(r) : "f"(x));
    return r;
}

// ---------------- input projection + LN stats --------------------------------
__global__ void __launch_bounds__(256) inproj_kernel(const float* __restrict__ x,
                                                     const float* __restrict__ in_w,
                                                     const float* __restrict__ in_b) {
    int row  = blockIdx.x * 8 + (threadIdx.x >> 5);
    int lane = threadIdx.x & 31;
    float x0 = __ldg(&x[row * 2]);
    float x1 = __ldg(&x[row * 2 + 1]);
    float s = 0.f, ss = 0.f;
    float* hr = g_h + (size_t)row * CH;
#pragma unroll
    for (int j = 0; j < 4; j++) {
        int c = lane + 32 * j;
        float h = fmaf(x0, in_w[c], fmaf(x1, in_w[CH + c], in_b[c]));
        hr[c] = h;
        s += h;
        ss = fmaf(h, h, ss);
    }
#pragma unroll
    for (int o = 16; o; o >>= 1) {
        s  += __shfl_xor_sync(0xffffffffu, s, o);
        ss += __shfl_xor_sync(0xffffffffu, ss, o);
    }
    if (lane == 0) {
        float mu  = s * (1.0f / CH);
        float var = fmaf(-mu, mu, ss * (1.0f / CH));
        g_stats[row] = make_float2(mu, rsqrtf(var + EPSLN));
    }
}

// ---------------- fused LN + QKV GEMM (R3 gemm<0> loop, LN in staging) -------
__global__ void __launch_bounds__(256) qkv_gemm(const float* __restrict__ W,
                                                const float* __restrict__ bias,
                                                const float* __restrict__ gam,
                                                const float* __restrict__ bet) {
    __shared__ float gsh[CH], bsh[CH];
    __shared__ float As[16][64];
    __shared__ float Bs[16][64];

    int tid = threadIdx.x;
    if (tid < 128) { gsh[tid] = gam[tid]; bsh[tid] = bet[tid]; }

    int tx  = tid & 15;
    int ty  = tid >> 4;

    ull acc[4][2];
#pragma unroll
    for (int m = 0; m < 4; m++) { acc[m][0] = 0ull; acc[m][1] = 0ull; }

    int ar = tid >> 2;
    int ac = (tid & 3) << 2;
    int br = tid >> 4;
    int bc = (tid & 15) << 2;

    size_t mBase = (size_t)blockIdx.y * 64;
    const float* Aload = g_h + (mBase + ar) * CH + ac;
    const float* Bload = W + (size_t)br * NQKV + blockIdx.x * 64 + bc;
    float2 st = g_stats[mBase + ar];
    float c1 = st.y;
    float c0 = -st.x * st.y;

    __syncthreads();

    for (int k0 = 0; k0 < CH; k0 += 16) {
        float4 av = *(const float4*)(Aload + k0);
        float4 bv = *(const float4*)(Bload + (size_t)k0 * NQKV);
        As[ac + 0][ar] = fmaf(fmaf(av.x, c1, c0), gsh[k0 + ac + 0], bsh[k0 + ac + 0]);
        As[ac + 1][ar] = fmaf(fmaf(av.y, c1, c0), gsh[k0 + ac + 1], bsh[k0 + ac + 1]);
        As[ac + 2][ar] = fmaf(fmaf(av.z, c1, c0), gsh[k0 + ac + 2], bsh[k0 + ac + 2]);
        As[ac + 3][ar] = fmaf(fmaf(av.w, c1, c0), gsh[k0 + ac + 3], bsh[k0 + ac + 3]);
        *(float4*)&Bs[br][bc] = bv;
        __syncthreads();
#pragma unroll
        for (int k = 0; k < 16; k++) {
            float4 b4 = *(const float4*)&Bs[k][tx << 2];
            ull b01 = pk2(b4.x, b4.y);
            ull b23 = pk2(b4.z, b4.w);
#pragma unroll
            for (int m = 0; m < 4; m++) {
                float a = As[k][(ty << 2) + m];
                ull aa = pk2(a, a);
                acc[m][0] = fma2(aa, b01, acc[m][0]);
                acc[m][1] = fma2(aa, b23, acc[m][1]);
            }
        }
        __syncthreads();
    }

    int col = blockIdx.x * 64 + (tx << 2);
    float4 bi = *(const float4*)(bias + col);
#pragma unroll
    for (int m = 0; m < 4; m++) {
        size_t row = mBase + (ty << 2) + m;
        float r0, r1, r2, r3;
        upk2(acc[m][0], r0, r1);
        upk2(acc[m][1], r2, r3);
        *(float4*)(g_qkv + row * NQKV + col) =
            make_float4(r0 + bi.x, r1 + bi.y, r2 + bi.z, r3 + bi.w);
    }
}

// ---------------- fused per-channel attention (R3-proven, unchanged) ---------
#define QT 9
#define KT 27
__global__ void __launch_bounds__(128, 8) attn_kernel() {
    int b  = blockIdx.y;
    int q0 = blockIdx.x * QT;
    int c  = threadIdx.x;

    __shared__ float ks[KT][CH];
    __shared__ float vs[KT][CH];

    const float* base = g_qkv + (size_t)b * SEQ * NQKV;
    const float LOG2E = 1.4426950408889634f;

    float qv[QT], num[QT], den[QT];
#pragma unroll
    for (int i = 0; i < QT; i++) {
        qv[i]  = base[(size_t)(q0 + i) * NQKV + c] * LOG2E;
        num[i] = 0.f;
        den[i] = 0.f;
    }

#pragma unroll 1
    for (int kc = 0; kc < SEQ; kc += KT) {
        __syncthreads();
#pragma unroll
        for (int r = 0; r < KT; r++) {
            ks[r][c] = base[(size_t)(kc + r) * NQKV + CH     + c];
            vs[r][c] = base[(size_t)(kc + r) * NQKV + 2 * CH + c];
        }
        __syncthreads();
#pragma unroll 3
        for (int r = 0; r < KT; r++) {
            float kk = ks[r][c];
            float vv = vs[r][c];
#pragma unroll
            for (int i = 0; i < QT; i++) {
                float e = ex2(qv[i] * kk);
                num[i] = fmaf(e, vv, num[i]);
                den[i] += e;
            }
        }
    }

    float* op = g_att + ((size_t)b * SEQ + q0) * CH + c;
#pragma unroll
    for (int i = 0; i < QT; i++) op[(size_t)i * CH] = __fdividef(num[i], den[i]);
}

// ---------------- full GEMM + relu + residual + stats partials ---------------
__global__ void __launch_bounds__(256) full_gemm(const float* __restrict__ B,
                                                 const float* __restrict__ bias) {
    __shared__ float As[16][64];
    __shared__ float Bs[16][64];

    int tid = threadIdx.x;
    int tx  = tid & 15;
    int ty  = tid >> 4;

    ull acc[4][2];
#pragma unroll
    for (int m = 0; m < 4; m++) { acc[m][0] = 0ull; acc[m][1] = 0ull; }

    int ar = tid >> 2;
    int ac = (tid & 3) << 2;
    int br = tid >> 4;
    int bc = (tid & 15) << 2;

    const float* Aload = g_att + ((size_t)blockIdx.y * 64 + ar) * CH + ac;
    const float* Bload = B + (size_t)br * CH + blockIdx.x * 64 + bc;

    for (int k0 = 0; k0 < CH; k0 += 16) {
        float4 av = *(const float4*)(Aload + k0);
        float4 bv = *(const float4*)(Bload + (size_t)k0 * CH);
        As[ac + 0][ar] = av.x;
        As[ac + 1][ar] = av.y;
        As[ac + 2][ar] = av.z;
        As[ac + 3][ar] = av.w;
        *(float4*)&Bs[br][bc] = bv;
        __syncthreads();
#pragma unroll
        for (int k = 0; k < 16; k++) {
            float4 b4 = *(const float4*)&Bs[k][tx << 2];
            ull b01 = pk2(b4.x, b4.y);
            ull b23 = pk2(b4.z, b4.w);
#pragma unroll
            for (int m = 0; m < 4; m++) {
                float a = As[k][(ty << 2) + m];
                ull aa = pk2(a, a);
                acc[m][0] = fma2(aa, b01, acc[m][0]);
                acc[m][1] = fma2(aa, b23, acc[m][1]);
            }
        }
        __syncthreads();
    }

    int col = blockIdx.x * 64 + (tx << 2);
    float4 bi = *(const float4*)(bias + col);
    float s[4], ss[4];
#pragma unroll
    for (int m = 0; m < 4; m++) {
        size_t row = (size_t)blockIdx.y * 64 + (ty << 2) + m;
        float r0, r1, r2, r3;
        upk2(acc[m][0], r0, r1);
        upk2(acc[m][1], r2, r3);
        r0 = fmaxf(r0 + bi.x, 0.f);
        r1 = fmaxf(r1 + bi.y, 0.f);
        r2 = fmaxf(r2 + bi.z, 0.f);
        r3 = fmaxf(r3 + bi.w, 0.f);
        float* hrow = g_h + row * CH + col;
        float4 old = *(const float4*)hrow;
        float h0 = old.x + r0, h1 = old.y + r1, h2 = old.z + r2, h3 = old.w + r3;
        *(float4*)hrow = make_float4(h0, h1, h2, h3);
        s[m]  = h0 + h1 + h2 + h3;
        ss[m] = fmaf(h0, h0, fmaf(h1, h1, fmaf(h2, h2, h3 * h3)));
    }
#pragma unroll
    for (int m = 0; m < 4; m++) {
#pragma unroll
        for (int o = 8; o; o >>= 1) {
            s[m]  += __shfl_xor_sync(0xffffffffu, s[m], o);
            ss[m] += __shfl_xor_sync(0xffffffffu, ss[m], o);
        }
    }
    if (tx == 0) {
#pragma unroll
        for (int m = 0; m < 4; m++) {
            size_t row = (size_t)blockIdx.y * 64 + (ty << 2) + m;
            float2* dst = (float2*)&g_part[row];        // two float2 halves
            dst[blockIdx.x] = make_float2(s[m], ss[m]); // block 0 -> .xy, 1 -> .zw
        }
    }
}

// finalize stats from the two 64-col partials (81*128 = 10368 = MROWS exactly)
__global__ void __launch_bounds__(128) finalize_stats() {
    int row = blockIdx.x * 128 + threadIdx.x;
    float4 p = g_part[row];
    float s  = p.x + p.z;
    float ss = p.y + p.w;
    float mu  = s * (1.0f / CH);
    float var = fmaf(-mu, mu, ss * (1.0f / CH));
    g_stats[row] = make_float2(mu, rsqrtf(var + EPSLN));
}

// ---------------- final projection: out = h @ out_w + out_b ------------------
__global__ void __launch_bounds__(256) outproj_kernel(const float* __restrict__ ow,
                                                      const float* __restrict__ ob,
                                                      float* __restrict__ out) {
    int row  = blockIdx.x * 8 + (threadIdx.x >> 5);
    int lane = threadIdx.x & 31;
    const float* hr = g_h + (size_t)row * CH;
    float a0 = 0.f, a1 = 0.f, a2 = 0.f, a3 = 0.f;
#pragma unroll
    for (int j = 0; j < 4; j++) {
        int cidx = lane + 32 * j;
        float hv = hr[cidx];
        const float* w = ow + cidx * 4;
        a0 = fmaf(hv, w[0], a0);
        a1 = fmaf(hv, w[1], a1);
        a2 = fmaf(hv, w[2], a2);
        a3 = fmaf(hv, w[3], a3);
    }
#pragma unroll
    for (int o = 16; o; o >>= 1) {
        a0 += __shfl_xor_sync(0xffffffffu, a0, o);
        a1 += __shfl_xor_sync(0xffffffffu, a1, o);
        a2 += __shfl_xor_sync(0xffffffffu, a2, o);
        a3 += __shfl_xor_sync(0xffffffffu, a3, o);
    }
    if (lane == 0) {
        *(float4*)(out + (size_t)row * 4) =
            make_float4(a0 + ob[0], a1 + ob[1], a2 + ob[2], a3 + ob[3]);
    }
}

// ---------------- launch -----------------------------------------------------
extern "C" void kernel_launch(void* const* d_in, const int* in_sizes, int n_in,
                              void* d_out, int out_size) {
    const float* x      = (const float*)d_in[0];
    const float* in_w   = (const float*)d_in[1];
    const float* in_b   = (const float*)d_in[2];
    const float* ln_g   = (const float*)d_in[3];
    const float* ln_b   = (const float*)d_in[4];
    const float* qkv_w  = (const float*)d_in[5];
    const float* qkv_b  = (const float*)d_in[6];
    const float* full_w = (const float*)d_in[7];
    const float* full_b = (const float*)d_in[8];
    const float* out_w  = (const float*)d_in[9];
    const float* out_b  = (const float*)d_in[10];
    float* out = (float*)d_out;

    inproj_kernel<<<MROWS / 8, 256>>>(x, in_w, in_b);

    for (int l = 0; l < 4; l++) {
        qkv_gemm<<<dim3(NQKV / 64, MROWS / 64), 256>>>(
            qkv_w + (size_t)l * CH * NQKV, qkv_b + l * NQKV,
            ln_g + l * CH, ln_b + l * CH);
        attn_kernel<<<dim3(SEQ / QT, TBS), 128>>>();
        full_gemm<<<dim3(CH / 64, MROWS / 64), 256>>>(
            full_w + (size_t)l * CH * CH, full_b + l * CH);
        if (l < 3) finalize_stats<<<MROWS / 128, 128>>>();
    }

    outproj_kernel<<<MROWS / 8, 256>>>(out_w, out_b, out);
}